// round 9
// baseline (speedup 1.0000x reference)
#include <cuda_runtime.h>

// Problem constants (fixed by setup_inputs)
#define BB 4
#define LL 256
#define DMM 256
#define DLL 64
#define RRR 256
#define NROWS (BB*LL)        // 1024
#define KCAT 512             // two rank-256 terms concatenated

// ---------------------------------------------------------------------------
// Scratch (device globals — no allocation allowed)
// ---------------------------------------------------------------------------
__device__ float g_qz[NROWS * DMM];     // masked softmax(x)           (1 MB)
__device__ float g_A [NROWS * KCAT];    // [A0 | A1] = qz @ [V0 | V1]  (2 MB)
__device__ float g_S [BB * KCAT];       // per-batch column sums of A
__device__ float g_sW[KCAT];            // (1/64) * sum_c W_t[c,d]
__device__ float g_B2[KCAT * DMM];      // packed [U0;U1]^T : row k=(t,d), col a

// ---------------------------------------------------------------------------
// Kernel 1: pack B2[k=(t*256+d)][a] = U[t][a][d]
// ---------------------------------------------------------------------------
__global__ __launch_bounds__(256) void k_pack_u(const float* __restrict__ U) {
    int i = blockIdx.x * blockDim.x + threadIdx.x;   // over 2*256*256
    if (i < 2 * DMM * RRR) {
        int t = i >> 16;
        int a = (i >> 8) & 255;
        int d = i & 255;
        g_B2[(t * 256 + d) * DMM + a] = U[i];
    }
}

// ---------------------------------------------------------------------------
// Kernel 2: sW[n=(t,d)] = (1/64) * sum_c W[t][c][d]
// ---------------------------------------------------------------------------
__global__ __launch_bounds__(256) void k_sw(const float* __restrict__ W) {
    int n = blockIdx.x * blockDim.x + threadIdx.x;   // over 512
    if (n < KCAT) {
        int t = n >> 8, d = n & 255;
        const float* w = W + t * DLL * RRR + d;
        float s = 0.0f;
        #pragma unroll 8
        for (int c = 0; c < DLL; c++) s += w[c * RRR];
        g_sW[n] = s * (1.0f / 64.0f);
    }
}

// ---------------------------------------------------------------------------
// Kernel 3: row softmax of x, zeroed where mask==0
// ---------------------------------------------------------------------------
__global__ __launch_bounds__(256) void k_softmax(const float* __restrict__ x,
                                                 const int* __restrict__ mask) {
    int row = blockIdx.x;            // 0..1023
    int tid = threadIdx.x;           // 0..255
    __shared__ float red[256];

    float v = x[row * DMM + tid];
    red[tid] = v;
    __syncthreads();
    for (int s = 128; s > 0; s >>= 1) {
        if (tid < s) red[tid] = fmaxf(red[tid], red[tid + s]);
        __syncthreads();
    }
    float m = red[0];
    __syncthreads();
    float e = __expf(v - m);
    red[tid] = e;
    __syncthreads();
    for (int s = 128; s > 0; s >>= 1) {
        if (tid < s) red[tid] += red[tid + s];
        __syncthreads();
    }
    float inv = 1.0f / red[0];
    g_qz[row * DMM + tid] = (mask[row] != 0) ? e * inv : 0.0f;
}

// ---------------------------------------------------------------------------
// Kernel 4: A = qz (1024x256) @ Vcat (256x512) -> g_A (1024x512)
// Vcat[b, n=(t,d)] = V[t][b][d]; a 64-wide N-tile never crosses the t boundary.
// Tile: BM=32, BN=64, BK=16, 256 threads, 2x4 accum/thread.
// ---------------------------------------------------------------------------
__global__ __launch_bounds__(256) void k_gemm1(const float* __restrict__ V) {
    __shared__ float As[16][33];      // +1 pad: kk-fast stores conflict-free
    __shared__ float Bs[16][64];

    int m0 = blockIdx.y * 32;
    int n0 = blockIdx.x * 64;
    int t  = n0 >> 8;
    int d0 = n0 & 255;
    const float* Bbase = V + t * DMM * RRR + d0;   // (k, nn) -> Bbase[k*256 + nn]

    int tid = threadIdx.x;
    int tx = tid & 15, ty = tid >> 4;
    float acc[2][4] = {};

    for (int k0 = 0; k0 < RRR; k0 += 16) {
        #pragma unroll
        for (int p = 0; p < 2; p++) {
            int idx = p * 256 + tid;
            int mm = idx >> 4, kk = idx & 15;
            As[kk][mm] = g_qz[(m0 + mm) * DMM + k0 + kk];
        }
        #pragma unroll
        for (int p = 0; p < 4; p++) {
            int idx = p * 256 + tid;
            int kk = idx >> 6, nn = idx & 63;
            Bs[kk][nn] = Bbase[(k0 + kk) * RRR + nn];
        }
        __syncthreads();
        #pragma unroll
        for (int kk = 0; kk < 16; kk++) {
            float a0 = As[kk][ty * 2 + 0];
            float a1 = As[kk][ty * 2 + 1];
            #pragma unroll
            for (int j = 0; j < 4; j++) {
                float b = Bs[kk][tx * 4 + j];
                acc[0][j] = fmaf(a0, b, acc[0][j]);
                acc[1][j] = fmaf(a1, b, acc[1][j]);
            }
        }
        __syncthreads();
    }
    #pragma unroll
    for (int r = 0; r < 2; r++)
        #pragma unroll
        for (int j = 0; j < 4; j++)
            g_A[(m0 + ty * 2 + r) * KCAT + n0 + tx * 4 + j] = acc[r][j];
}

// ---------------------------------------------------------------------------
// Kernel 5: S[z, n] = sum_j A[z*256 + j, n]
// ---------------------------------------------------------------------------
__global__ __launch_bounds__(256) void k_colsum() {
    int g = blockIdx.x * blockDim.x + threadIdx.x;   // over 4*512 = 2048
    if (g < BB * KCAT) {
        int z = g >> 9, n = g & 511;
        const float* p = g_A + z * LL * KCAT + n;
        float s = 0.0f;
        #pragma unroll 8
        for (int j = 0; j < LL; j++) s += p[j * KCAT];
        g_S[g] = s;
    }
}

// ---------------------------------------------------------------------------
// Kernel 6: out = x + valid * ( T (1024x512) @ B2 (512x256) )
//           T[row,k] = (S[z,k] - A[row,k]) * sW[k]   (computed on load)
// Tile: BM=32, BN=64, BK=16.
// ---------------------------------------------------------------------------
__global__ __launch_bounds__(256) void k_gemm2(const float* __restrict__ x,
                                               const int* __restrict__ mask,
                                               float* __restrict__ out) {
    __shared__ float As[16][33];
    __shared__ float Bs[16][64];

    int m0 = blockIdx.y * 32;
    int n0 = blockIdx.x * 64;
    int z  = m0 >> 8;                 // 32 | 256 -> constant per block

    int tid = threadIdx.x;
    int tx = tid & 15, ty = tid >> 4;
    float acc[2][4] = {};

    for (int k0 = 0; k0 < KCAT; k0 += 16) {
        #pragma unroll
        for (int p = 0; p < 2; p++) {
            int idx = p * 256 + tid;
            int mm = idx >> 4, kk = idx & 15;
            int k = k0 + kk;
            As[kk][mm] = (g_S[z * KCAT + k] - g_A[(m0 + mm) * KCAT + k]) * g_sW[k];
        }
        #pragma unroll
        for (int p = 0; p < 4; p++) {
            int idx = p * 256 + tid;
            int kk = idx >> 6, nn = idx & 63;
            Bs[kk][nn] = g_B2[(k0 + kk) * DMM + n0 + nn];
        }
        __syncthreads();
        #pragma unroll
        for (int kk = 0; kk < 16; kk++) {
            float a0 = As[kk][ty * 2 + 0];
            float a1 = As[kk][ty * 2 + 1];
            #pragma unroll
            for (int j = 0; j < 4; j++) {
                float b = Bs[kk][tx * 4 + j];
                acc[0][j] = fmaf(a0, b, acc[0][j]);
                acc[1][j] = fmaf(a1, b, acc[1][j]);
            }
        }
        __syncthreads();
    }

    #pragma unroll
    for (int r = 0; r < 2; r++) {
        int row = m0 + ty * 2 + r;
        float mv = (mask[row] != 0) ? 1.0f : 0.0f;
        #pragma unroll
        for (int j = 0; j < 4; j++) {
            int col = n0 + tx * 4 + j;
            out[row * DMM + col] = x[row * DMM + col] + mv * acc[r][j];
        }
    }
}

// ---------------------------------------------------------------------------
// Launch
// Inputs (metadata order): x (f32, 262144), U (f32, 131072), V (f32, 131072),
//                          W (f32, 32768),  mask (i32, 1024)
// Output: f32, 262144 = x + F
// ---------------------------------------------------------------------------
extern "C" void kernel_launch(void* const* d_in, const int* in_sizes, int n_in,
                              void* d_out, int out_size) {
    (void)in_sizes; (void)n_in; (void)out_size;
    const float* x    = (const float*)d_in[0];
    const float* U    = (const float*)d_in[1];
    const float* V    = (const float*)d_in[2];
    const float* W    = (const float*)d_in[3];
    const int*   mask = (const int*)d_in[4];
    float* out = (float*)d_out;

    k_pack_u<<<(2 * DMM * RRR + 255) / 256, 256>>>(U);
    k_sw<<<2, 256>>>(W);
    k_softmax<<<NROWS, 256>>>(x, mask);
    k_gemm1<<<dim3(KCAT / 64, NROWS / 32), 256>>>(V);
    k_colsum<<<(BB * KCAT + 255) / 256, 256>>>();
    k_gemm2<<<dim3(DMM / 64, NROWS / 32), 256>>>(x, mask, out);
}

// round 10
// speedup vs baseline: 1.6581x; 1.6581x over previous
#include <cuda_runtime.h>

// Problem constants (fixed by setup_inputs)
#define BB 4
#define LL 256
#define DMM 256
#define DLL 64
#define RRR 256
#define NROWS (BB*LL)        // 1024
#define KCAT 512             // two rank-256 terms concatenated

// ---------------------------------------------------------------------------
// Scratch (device globals — no allocation allowed)
// ---------------------------------------------------------------------------
__device__ float g_qz[NROWS * DMM];     // masked softmax(x)           (1 MB)
__device__ float g_A [NROWS * KCAT];    // [A0 | A1] = qz @ [V0 | V1]  (2 MB)
__device__ float g_S [BB * KCAT];       // per-batch column sums of A
__device__ float g_sW[KCAT];            // (1/64) * sum_c W_t[c,d]

// ---------------------------------------------------------------------------
// Kernel 1 (fused): blocks [0,1024) = masked row softmax of x -> g_qz
//                   blocks [1024,1026) = sW[n=(t,d)] = (1/64)*sum_c W[t][c][d]
// ---------------------------------------------------------------------------
__global__ __launch_bounds__(256) void k_pre(const float* __restrict__ x,
                                             const int* __restrict__ mask,
                                             const float* __restrict__ W) {
    int tid = threadIdx.x;

    if (blockIdx.x >= 1024) {
        int n = (blockIdx.x - 1024) * 256 + tid;     // 0..511
        int t = n >> 8, d = n & 255;
        const float* w = W + t * DLL * RRR + d;
        float s = 0.0f;
        #pragma unroll 8
        for (int c = 0; c < DLL; c++) s += w[c * RRR];
        g_sW[n] = s * (1.0f / 64.0f);
        return;
    }

    int row = blockIdx.x;
    int lane = tid & 31, wid = tid >> 5;
    __shared__ float wred[16];

    float v = x[row * DMM + tid];

    // warp max, then cross-warp via smem
    float m = v;
    #pragma unroll
    for (int off = 16; off > 0; off >>= 1)
        m = fmaxf(m, __shfl_xor_sync(0xFFFFFFFFu, m, off));
    if (lane == 0) wred[wid] = m;
    __syncthreads();
    float bm = wred[0];
    #pragma unroll
    for (int i = 1; i < 8; i++) bm = fmaxf(bm, wred[i]);

    float e = __expf(v - bm);
    float s = e;
    #pragma unroll
    for (int off = 16; off > 0; off >>= 1)
        s += __shfl_xor_sync(0xFFFFFFFFu, s, off);
    if (lane == 0) wred[8 + wid] = s;
    __syncthreads();
    float bs = 0.0f;
    #pragma unroll
    for (int i = 0; i < 8; i++) bs += wred[8 + i];

    g_qz[row * DMM + tid] = (mask[row] != 0) ? e * (1.0f / bs) : 0.0f;
}

// ---------------------------------------------------------------------------
// Kernel 2: A = qz (1024x256) @ Vcat (256x512) -> g_A (1024x512)
// Vcat[k, n=(t,d)] = V[t][k][d]. Tiles 64x64x16, 256 thr, 4x4 acc/thread,
// double-buffered smem + register prefetch: one __syncthreads per k-block.
// Grid (8, 16) = 128 blocks = one wave.
// ---------------------------------------------------------------------------
__global__ __launch_bounds__(256) void k_gemm1(const float* __restrict__ V) {
    __shared__ __align__(16) float As[2][16][68];   // [kk][mm], pad 68
    __shared__ __align__(16) float Bs[2][16][64];   // [kk][nn]

    const int m0 = blockIdx.y * 64;
    const int n0 = blockIdx.x * 64;
    const float* Bbase = V + (n0 >> 8) * (DMM * RRR) + (n0 & 255);

    const int tid = threadIdx.x;
    const int tx = tid & 15, ty = tid >> 4;
    const int a_kk = tid & 15, a_mm = tid >> 4;     // +16 per p
    const int b_nn = tid & 63, b_kk = tid >> 6;     // +4 per p

    float acc[4][4] = {};
    float ar[4], br[4];

    // prologue: k-block 0
    #pragma unroll
    for (int p = 0; p < 4; p++)
        ar[p] = g_qz[(m0 + a_mm + p * 16) * DMM + a_kk];
    #pragma unroll
    for (int p = 0; p < 4; p++)
        br[p] = Bbase[(b_kk + p * 4) * RRR + b_nn];
    #pragma unroll
    for (int p = 0; p < 4; p++) As[0][a_kk][a_mm + p * 16] = ar[p];
    #pragma unroll
    for (int p = 0; p < 4; p++) Bs[0][b_kk + p * 4][b_nn] = br[p];
    __syncthreads();

    int buf = 0;
    for (int kb = 0; kb < 16; kb++) {
        const int k0n = (kb + 1) * 16;
        if (kb < 15) {
            #pragma unroll
            for (int p = 0; p < 4; p++)
                ar[p] = g_qz[(m0 + a_mm + p * 16) * DMM + k0n + a_kk];
            #pragma unroll
            for (int p = 0; p < 4; p++)
                br[p] = Bbase[(k0n + b_kk + p * 4) * RRR + b_nn];
        }
        #pragma unroll
        for (int kk = 0; kk < 16; kk++) {
            float4 a = *(const float4*)&As[buf][kk][ty * 4];
            float4 b = *(const float4*)&Bs[buf][kk][tx * 4];
            float av[4] = {a.x, a.y, a.z, a.w};
            float bv[4] = {b.x, b.y, b.z, b.w};
            #pragma unroll
            for (int i = 0; i < 4; i++)
                #pragma unroll
                for (int j = 0; j < 4; j++)
                    acc[i][j] = fmaf(av[i], bv[j], acc[i][j]);
        }
        if (kb < 15) {
            #pragma unroll
            for (int p = 0; p < 4; p++) As[buf ^ 1][a_kk][a_mm + p * 16] = ar[p];
            #pragma unroll
            for (int p = 0; p < 4; p++) Bs[buf ^ 1][b_kk + p * 4][b_nn] = br[p];
            __syncthreads();
            buf ^= 1;
        }
    }

    #pragma unroll
    for (int i = 0; i < 4; i++) {
        float4 v = make_float4(acc[i][0], acc[i][1], acc[i][2], acc[i][3]);
        *(float4*)&g_A[(m0 + ty * 4 + i) * KCAT + n0 + tx * 4] = v;
    }
}

// ---------------------------------------------------------------------------
// Kernel 3: S[z, n] = sum_j A[z*256 + j, n].  Grid 32 x 256 thr.
// Block b handles 64 (z,n) pairs; 4 threads split the 256-row sum.
// ---------------------------------------------------------------------------
__global__ __launch_bounds__(256) void k_colsum() {
    __shared__ float red[256];
    int t = threadIdx.x;
    int pair0 = blockIdx.x * 64;
    int pr = pair0 + (t & 63);          // (z,n) pair index: pr = z*512 + n
    int q = t >> 6;                     // row quarter 0..3
    int z = pr >> 9, n = pr & 511;
    const float* p = g_A + (z * LL + q * 64) * KCAT + n;
    float s = 0.0f;
    #pragma unroll 8
    for (int j = 0; j < 64; j++) s += p[j * KCAT];
    red[t] = s;
    __syncthreads();
    if (t < 64)
        g_S[pair0 + t] = red[t] + red[t + 64] + red[t + 128] + red[t + 192];
}

// ---------------------------------------------------------------------------
// Kernel 4: out = x + valid * ( T (1024x512) @ B2 (512x256) )
//   T[row,k]  = S[z,k]*sW[k] - A[row,k]*sW[k]   (Ssw/sW staged in smem)
//   B2[k][a]  = U[t][a][d],  k = t*256+d        (loaded straight from U)
// Tiles 64x32x16, 256 thr, 2x4 acc/thread, double-buffered.
// Grid (8, 16) = 128 blocks = one wave.
// ---------------------------------------------------------------------------
__global__ __launch_bounds__(256) void k_gemm2(const float* __restrict__ x,
                                               const int* __restrict__ mask,
                                               const float* __restrict__ U,
                                               float* __restrict__ out) {
    __shared__ __align__(16) float As[2][16][66];   // [kk][mm], pad 66
    __shared__ __align__(16) float Bs[2][16][32];   // [kk][nn]
    __shared__ float Ssw[KCAT];
    __shared__ float Ws[KCAT];

    const int m0 = blockIdx.y * 64;
    const int n0 = blockIdx.x * 32;
    const int z  = m0 >> 8;
    const int tid = threadIdx.x;

    #pragma unroll
    for (int i = tid; i < KCAT; i += 256) {
        float w = g_sW[i];
        Ws[i]  = w;
        Ssw[i] = g_S[z * KCAT + i] * w;
    }
    __syncthreads();

    const int tx = tid & 7, ty = tid >> 3;          // tx: 8x4 cols, ty: 32x2 rows
    const int a_kk = tid & 15, a_mm = tid >> 4;     // +16 per p (4 ps)
    const int b_kk = tid & 15, b_nn = tid >> 4;     // +16 per p (2 ps)

    float acc[2][4] = {};
    float ar[4], br[2];

    // prologue: k-block 0 (k0 = 0 -> t = 0, dbase = 0)
    #pragma unroll
    for (int p = 0; p < 4; p++)
        ar[p] = g_A[(m0 + a_mm + p * 16) * KCAT + a_kk];
    #pragma unroll
    for (int p = 0; p < 2; p++)
        br[p] = U[(n0 + b_nn + p * 16) * RRR + b_kk];
    #pragma unroll
    for (int p = 0; p < 4; p++)
        As[0][a_kk][a_mm + p * 16] = Ssw[a_kk] - ar[p] * Ws[a_kk];
    #pragma unroll
    for (int p = 0; p < 2; p++) Bs[0][b_kk][b_nn + p * 16] = br[p];
    __syncthreads();

    int buf = 0;
    for (int kb = 0; kb < 32; kb++) {
        const int k0n = (kb + 1) * 16;
        if (kb < 31) {
            const float* Ub = U + (k0n >> 8) * (DMM * RRR) + (k0n & 255);
            #pragma unroll
            for (int p = 0; p < 4; p++)
                ar[p] = g_A[(m0 + a_mm + p * 16) * KCAT + k0n + a_kk];
            #pragma unroll
            for (int p = 0; p < 2; p++)
                br[p] = Ub[(n0 + b_nn + p * 16) * RRR + b_kk];
        }
        #pragma unroll
        for (int kk = 0; kk < 16; kk++) {
            float2 a = *(const float2*)&As[buf][kk][ty * 2];
            float4 b = *(const float4*)&Bs[buf][kk][tx * 4];
            float av[2] = {a.x, a.y};
            float bv[4] = {b.x, b.y, b.z, b.w};
            #pragma unroll
            for (int i = 0; i < 2; i++)
                #pragma unroll
                for (int j = 0; j < 4; j++)
                    acc[i][j] = fmaf(av[i], bv[j], acc[i][j]);
        }
        if (kb < 31) {
            #pragma unroll
            for (int p = 0; p < 4; p++)
                As[buf ^ 1][a_kk][a_mm + p * 16] =
                    Ssw[k0n + a_kk] - ar[p] * Ws[k0n + a_kk];
            #pragma unroll
            for (int p = 0; p < 2; p++) Bs[buf ^ 1][b_kk][b_nn + p * 16] = br[p];
            __syncthreads();
            buf ^= 1;
        }
    }

    #pragma unroll
    for (int i = 0; i < 2; i++) {
        int row = m0 + ty * 2 + i;
        float mv = (mask[row] != 0) ? 1.0f : 0.0f;
        float4 xv = *(const float4*)&x[row * DMM + n0 + tx * 4];
        float4 ov = make_float4(fmaf(mv, acc[i][0], xv.x),
                                fmaf(mv, acc[i][1], xv.y),
                                fmaf(mv, acc[i][2], xv.z),
                                fmaf(mv, acc[i][3], xv.w));
        *(float4*)&out[row * DMM + n0 + tx * 4] = ov;
    }
}

// ---------------------------------------------------------------------------
// Launch
// Inputs (metadata order): x (f32, 262144), U (f32, 131072), V (f32, 131072),
//                          W (f32, 32768),  mask (i32, 1024)
// ---------------------------------------------------------------------------
extern "C" void kernel_launch(void* const* d_in, const int* in_sizes, int n_in,
                              void* d_out, int out_size) {
    (void)in_sizes; (void)n_in; (void)out_size;
    const float* x    = (const float*)d_in[0];
    const float* U    = (const float*)d_in[1];
    const float* V    = (const float*)d_in[2];
    const float* W    = (const float*)d_in[3];
    const int*   mask = (const int*)d_in[4];
    float* out = (float*)d_out;

    k_pre<<<1026, 256>>>(x, mask, W);
    k_gemm1<<<dim3(KCAT / 64, NROWS / 64), 256>>>(V);
    k_colsum<<<32, 256>>>();
    k_gemm2<<<dim3(DMM / 32, NROWS / 64), 256>>>(x, mask, U, out);
}

// round 12
// speedup vs baseline: 3.1319x; 1.8889x over previous
#include <cuda_runtime.h>

// Problem constants (fixed by setup_inputs)
#define BB 4
#define LL 256
#define DMM 256
#define DLL 64
#define RRR 256
#define NROWS (BB*LL)        // 1024
#define KCAT 512

// ---------------------------------------------------------------------------
// Scratch (device globals — no allocation allowed)
// ---------------------------------------------------------------------------
__device__ float g_qz[NROWS * DMM];     // masked softmax(x)          (1 MB)
__device__ float g_sW[KCAT];            // (1/64) * sum_c W_t[c,d]
__device__ float g_u [BB * DMM];        // u[z,b] = sum_j qz[z,j,b]
__device__ float g_Mp[2 * DMM * DMM];   // Mp[t][b][a]; M = Mp[0]+Mp[1]

// ---------------------------------------------------------------------------
// Kernel 1 (fused): blocks [0,1024) = masked row softmax of x -> g_qz
//                   blocks [1024,1026) = sW[n=(t,d)] = (1/64)*sum_c W[t][c][d]
// ---------------------------------------------------------------------------
__global__ __launch_bounds__(256) void k_pre(const float* __restrict__ x,
                                             const int* __restrict__ mask,
                                             const float* __restrict__ W) {
    int tid = threadIdx.x;

    if (blockIdx.x >= 1024) {
        int n = (blockIdx.x - 1024) * 256 + tid;     // 0..511
        int t = n >> 8, d = n & 255;
        const float* w = W + t * DLL * RRR + d;
        float s = 0.0f;
        #pragma unroll 8
        for (int c = 0; c < DLL; c++) s += w[c * RRR];
        g_sW[n] = s * (1.0f / 64.0f);
        return;
    }

    int row = blockIdx.x;
    int lane = tid & 31, wid = tid >> 5;
    __shared__ float wred[16];

    float v = x[row * DMM + tid];

    float m = v;
    #pragma unroll
    for (int off = 16; off > 0; off >>= 1)
        m = fmaxf(m, __shfl_xor_sync(0xFFFFFFFFu, m, off));
    if (lane == 0) wred[wid] = m;
    __syncthreads();
    float bm = wred[0];
    #pragma unroll
    for (int i = 1; i < 8; i++) bm = fmaxf(bm, wred[i]);

    float e = __expf(v - bm);
    float s = e;
    #pragma unroll
    for (int off = 16; off > 0; off >>= 1)
        s += __shfl_xor_sync(0xFFFFFFFFu, s, off);
    if (lane == 0) wred[8 + wid] = s;
    __syncthreads();
    float bs = 0.0f;
    #pragma unroll
    for (int i = 0; i < 8; i++) bs += wred[8 + i];

    g_qz[row * DMM + tid] = (mask[row] != 0) ? e * (1.0f / bs) : 0.0f;
}

// ---------------------------------------------------------------------------
// Kernel 2 (fused):
//  blocks [0,128):  Mp[t][b][a] = sum_d V[t][b][d]*sW[t*256+d]*U[t][a][d]
//                   (NT GEMM 256x256x256 per t; 32x32 tiles, 2x2 acc,
//                    double-buffered smem + register prefetch)
//  blocks [128,160): u[z,b] = sum_j qz[z,j,b]
// ---------------------------------------------------------------------------
__global__ __launch_bounds__(256) void k_mid(const float* __restrict__ U,
                                             const float* __restrict__ V) {
    __shared__ __align__(16) float As[2][32][34];   // even pad: float2-safe
    __shared__ __align__(16) float Bs[2][32][34];
    __shared__ float sWs[256];

    int tid = threadIdx.x;

    if (blockIdx.x >= 128) {                 // ---- u part ----
        int b = blockIdx.x - 128;            // 0..31
        int z = b >> 3;
        int c0 = (b & 7) * 32;
        int col = c0 + (tid & 31);
        int rg = tid >> 5;                   // 0..7
        const float* p = g_qz + (z * LL + rg * 32) * DMM + col;
        float s = 0.0f;
        #pragma unroll 8
        for (int j = 0; j < 32; j++) s += p[j * DMM];
        float* red = &As[0][0][0];           // reuse smem
        red[tid] = s;
        __syncthreads();
        if (tid < 32) {
            float t = 0.0f;
            #pragma unroll
            for (int g = 0; g < 8; g++) t += red[g * 32 + tid];
            g_u[z * DMM + c0 + tid] = t;
        }
        return;
    }

    // ---- Mp part ----
    const int bx = blockIdx.x;
    const int t  = bx >> 6;
    const int b0 = ((bx >> 3) & 7) * 32;
    const int a0 = (bx & 7) * 32;
    const float* Vt = V + t * (DMM * RRR);
    const float* Ut = U + t * (DMM * RRR);

    sWs[tid] = g_sW[t * 256 + tid];
    __syncthreads();

    const int kk = tid & 31, rr = tid >> 5;      // loads: +8 per p
    const int tx = tid & 15, ty = tid >> 4;      // compute: 16x16, 2x2 acc

    float acc[2][2] = {};
    float ar[4], br[4];

    // prologue kb = 0
    #pragma unroll
    for (int p = 0; p < 4; p++) {
        ar[p] = Vt[(b0 + rr + 8 * p) * RRR + kk];
        br[p] = Ut[(a0 + rr + 8 * p) * RRR + kk];
    }
    #pragma unroll
    for (int p = 0; p < 4; p++) {
        As[0][kk][rr + 8 * p] = ar[p] * sWs[kk];
        Bs[0][kk][rr + 8 * p] = br[p];
    }
    __syncthreads();

    int buf = 0;
    for (int kb = 0; kb < 8; kb++) {
        const int k0n = (kb + 1) * 32;
        if (kb < 7) {
            #pragma unroll
            for (int p = 0; p < 4; p++) {
                ar[p] = Vt[(b0 + rr + 8 * p) * RRR + k0n + kk];
                br[p] = Ut[(a0 + rr + 8 * p) * RRR + k0n + kk];
            }
        }
        #pragma unroll
        for (int k2 = 0; k2 < 32; k2++) {
            float2 a = *(const float2*)&As[buf][k2][ty * 2];
            float2 b = *(const float2*)&Bs[buf][k2][tx * 2];
            acc[0][0] = fmaf(a.x, b.x, acc[0][0]);
            acc[0][1] = fmaf(a.x, b.y, acc[0][1]);
            acc[1][0] = fmaf(a.y, b.x, acc[1][0]);
            acc[1][1] = fmaf(a.y, b.y, acc[1][1]);
        }
        if (kb < 7) {
            #pragma unroll
            for (int p = 0; p < 4; p++) {
                As[buf ^ 1][kk][rr + 8 * p] = ar[p] * sWs[k0n + kk];
                Bs[buf ^ 1][kk][rr + 8 * p] = br[p];
            }
            __syncthreads();
            buf ^= 1;
        }
    }

    #pragma unroll
    for (int i = 0; i < 2; i++) {
        float2 v2 = make_float2(acc[i][0], acc[i][1]);
        *(float2*)&g_Mp[t * (DMM * DMM) + (b0 + ty * 2 + i) * DMM + a0 + tx * 2] = v2;
    }
}

// ---------------------------------------------------------------------------
// Kernel 3: out[row,a] = x[row,a] + valid_row * sum_k (u[z,k]-qz[row,k]) * M[k,a]
//           M[k,a] = Mp[0][k,a] + Mp[1][k,a]  (summed during B staging)
// Tiles 32(m) x 64(a), K=256 (BK=32, 8 k-blocks), 2x4 acc, double-buffered.
// Grid 128 = one wave.
// ---------------------------------------------------------------------------
__global__ __launch_bounds__(256) void k_out(const float* __restrict__ x,
                                             const int* __restrict__ mask,
                                             float* __restrict__ out) {
    __shared__ __align__(16) float As[2][32][34];   // even pad: float2-safe
    __shared__ __align__(16) float Bs[2][32][64];   // [kk][aa]
    __shared__ float us[256];

    const int bx = blockIdx.x;
    const int m0 = (bx >> 2) * 32;
    const int a0 = (bx & 3) * 64;
    const int z  = m0 >> 8;
    const int tid = threadIdx.x;

    us[tid] = g_u[z * DMM + tid];
    __syncthreads();

    const int a_kk = tid & 31, a_mm = tid >> 5;     // A loads: +8 per p (4 ps)
    const int b_aa = tid & 63, b_kk = tid >> 6;     // B loads: +4 per p (8 ps)
    const int tx = tid & 15, ty = tid >> 4;         // compute: 2 rows x 4 cols

    float acc[2][4] = {};
    float ar[4], brA[8], brB[8];

    // prologue kb = 0
    #pragma unroll
    for (int p = 0; p < 4; p++)
        ar[p] = g_qz[(m0 + a_mm + 8 * p) * DMM + a_kk];
    #pragma unroll
    for (int p = 0; p < 8; p++) {
        int idx = (b_kk + 4 * p) * DMM + a0 + b_aa;
        brA[p] = g_Mp[idx];
        brB[p] = g_Mp[idx + DMM * DMM];
    }
    #pragma unroll
    for (int p = 0; p < 4; p++)
        As[0][a_kk][a_mm + 8 * p] = us[a_kk] - ar[p];
    #pragma unroll
    for (int p = 0; p < 8; p++)
        Bs[0][b_kk + 4 * p][b_aa] = brA[p] + brB[p];
    __syncthreads();

    int buf = 0;
    for (int kb = 0; kb < 8; kb++) {
        const int k0n = (kb + 1) * 32;
        if (kb < 7) {
            #pragma unroll
            for (int p = 0; p < 4; p++)
                ar[p] = g_qz[(m0 + a_mm + 8 * p) * DMM + k0n + a_kk];
            #pragma unroll
            for (int p = 0; p < 8; p++) {
                int idx = (k0n + b_kk + 4 * p) * DMM + a0 + b_aa;
                brA[p] = g_Mp[idx];
                brB[p] = g_Mp[idx + DMM * DMM];
            }
        }
        #pragma unroll
        for (int k2 = 0; k2 < 32; k2++) {
            float2 a = *(const float2*)&As[buf][k2][ty * 2];
            float4 b = *(const float4*)&Bs[buf][k2][tx * 4];
            float av[2] = {a.x, a.y};
            float bv[4] = {b.x, b.y, b.z, b.w};
            #pragma unroll
            for (int i = 0; i < 2; i++)
                #pragma unroll
                for (int j = 0; j < 4; j++)
                    acc[i][j] = fmaf(av[i], bv[j], acc[i][j]);
        }
        if (kb < 7) {
            #pragma unroll
            for (int p = 0; p < 4; p++)
                As[buf ^ 1][a_kk][a_mm + 8 * p] = us[k0n + a_kk] - ar[p];
            #pragma unroll
            for (int p = 0; p < 8; p++)
                Bs[buf ^ 1][b_kk + 4 * p][b_aa] = brA[p] + brB[p];
            __syncthreads();
            buf ^= 1;
        }
    }

    #pragma unroll
    for (int i = 0; i < 2; i++) {
        int row = m0 + ty * 2 + i;
        float mv = (mask[row] != 0) ? 1.0f : 0.0f;
        float4 xv = *(const float4*)&x[row * DMM + a0 + tx * 4];
        float4 ov = make_float4(fmaf(mv, acc[i][0], xv.x),
                                fmaf(mv, acc[i][1], xv.y),
                                fmaf(mv, acc[i][2], xv.z),
                                fmaf(mv, acc[i][3], xv.w));
        *(float4*)&out[row * DMM + a0 + tx * 4] = ov;
    }
}

// ---------------------------------------------------------------------------
// Launch
// Inputs (metadata order): x (f32, 262144), U (f32, 131072), V (f32, 131072),
//                          W (f32, 32768),  mask (i32, 1024)
// ---------------------------------------------------------------------------
extern "C" void kernel_launch(void* const* d_in, const int* in_sizes, int n_in,
                              void* d_out, int out_size) {
    (void)in_sizes; (void)n_in; (void)out_size;
    const float* x    = (const float*)d_in[0];
    const float* U    = (const float*)d_in[1];
    const float* V    = (const float*)d_in[2];
    const float* W    = (const float*)d_in[3];
    const int*   mask = (const int*)d_in[4];
    float* out = (float*)d_out;

    k_pre<<<1026, 256>>>(x, mask, W);
    k_mid<<<160, 256>>>(U, V);
    k_out<<<128, 256>>>(x, mask, out);
}